// round 7
// baseline (speedup 1.0000x reference)
#include <cuda_runtime.h>
#include <cuda_bf16.h>
#include <math.h>

#define Fn 500
#define Hn 2000
#define FH 2500
#define Dn 64
#define Bn 4096
#define NB 888       // 6 CTAs/SM x 148 SMs, 128 threads: co-resident

// Scratch
__device__ __align__(16) float g_pre_f[Fn * Dn];
__device__ __align__(16) float g_pre_w[FH * Dn];
__device__ __align__(16) float g_P1[Fn * Dn];   // wu * a^2
__device__ __align__(16) float g_P2[Fn * Dn];   // wu * a
__device__ __align__(16) float g_ctx[Fn * Dn];
__device__ float g_B[FH];                       // B_j = sum wu*(b - b^3/3)
__device__ float g_pwmax[FH];                   // row max |b|
__device__ float g_amax[Fn];                    // row max |a|

// Replay-safe grid barrier
__device__ unsigned g_count = 0;
__device__ unsigned g_gen   = 0;

__device__ __forceinline__ void grid_bar() {
    __threadfence();
    __syncthreads();
    if (threadIdx.x == 0) {
        unsigned gen = atomicAdd(&g_gen, 0u);
        if (atomicAdd(&g_count, 1u) == NB - 1u) {
            g_count = 0u;
            __threadfence();
            atomicAdd(&g_gen, 1u);
        } else {
            while (atomicAdd(&g_gen, 0u) == gen) __nanosleep(32);
        }
    }
    __syncthreads();
}

typedef unsigned long long ull;
__device__ __forceinline__ ull pk2(float a, float b) {
    ull r; asm("mov.b64 %0, {%1,%2};" : "=l"(r) : "f"(a), "f"(b)); return r;
}
__device__ __forceinline__ void upk2(ull v, float& a, float& b) {
    asm("mov.b64 {%0,%1}, %2;" : "=f"(a), "=f"(b) : "l"(v));
}
__device__ __forceinline__ ull f2fma(ull a, ull b, ull c) {
    ull d; asm("fma.rn.f32x2 %0, %1, %2, %3;" : "=l"(d) : "l"(a), "l"(b), "l"(c)); return d;
}
__device__ __forceinline__ ull f2mul(ull a, ull b) {
    ull d; asm("mul.rn.f32x2 %0, %1, %2;" : "=l"(d) : "l"(a), "l"(b)); return d;
}
__device__ __forceinline__ const float* full_row(const float* feat,
                                                 const float* hid, int j) {
    return (j < Fn) ? (feat + j * Dn) : (hid + (j - Fn) * Dn);
}

#define TFk 50
struct __align__(16) S1 {
    float sx[2][Dn];
    float red[4];
    float rmax[4];
};
struct __align__(16) S2 {
    float elist[FH];
    unsigned short jlist[FH];
    __align__(16) float P1[Dn];
    __align__(16) float P2[Dn];
    __align__(16) float pf[Dn];
    __align__(16) float wu[Dn];
    float part[2][Dn];
    int   warpbase[5];
    float wsum[4];
    float red4[4];
    float swu_s, mxb_s, inv;
    int   level;
};
struct __align__(16) S3 {
    float val[8][TFk];
    float ctx[TFk][Dn];
};
union SMem { S1 s1; S2 s2; S3 s3; };

__global__ __launch_bounds__(128, 6) void fused_all(
    const float* __restrict__ values,
    const float* __restrict__ feat,
    const float* __restrict__ hid,
    const float* __restrict__ Ww,
    const float* __restrict__ bw,
    const float* __restrict__ Wu,
    const float* __restrict__ mask,
    float* __restrict__ out)
{
    __shared__ SMem sm;
    const int tid  = threadIdx.x;
    const int wid  = tid >> 5;
    const int lane = tid & 31;

    // ============ Stage 1: projections + B_j + P1/P2 + row maxes ============
    {
        const int r = tid >> 6;     // 0/1: row within task
        const int a = tid & 63;     // column
        for (int t = blockIdx.x; t < 1500; t += NB) {
            __syncthreads();
            if (t < 1250) {
                const int row = t * 2 + r;                     // 0..2499
                float v = (row < Fn) ? feat[row * Dn + a]
                                     : hid[(row - Fn) * Dn + a];
                sm.s1.sx[r][a] = v;
                __syncthreads();
                float b = 0.f;
                #pragma unroll
                for (int k = 0; k < Dn; k++)
                    b += sm.s1.sx[r][k] * __ldg(&Ww[(Dn + k) * Dn + a]);
                g_pre_w[row * Dn + a] = b;
                const float wua = __ldg(&Wu[a]);
                float term = wua * (b - b * b * b * 0.33333334f);
                float mm = fabsf(b);
                #pragma unroll
                for (int off = 16; off > 0; off >>= 1) {
                    term += __shfl_xor_sync(0xffffffffu, term, off);
                    mm = fmaxf(mm, __shfl_xor_sync(0xffffffffu, mm, off));
                }
                if (lane == 0) { sm.s1.red[wid] = term; sm.s1.rmax[wid] = mm; }
                __syncthreads();
                if (tid == 0) {
                    g_B[row]     = sm.s1.red[0] + sm.s1.red[1];
                    g_pwmax[row] = fmaxf(sm.s1.rmax[0], sm.s1.rmax[1]);
                } else if (tid == 64) {
                    g_B[row]     = sm.s1.red[2] + sm.s1.red[3];
                    g_pwmax[row] = fmaxf(sm.s1.rmax[2], sm.s1.rmax[3]);
                }
            } else {
                const int row = (t - 1250) * 2 + r;            // 0..499
                sm.s1.sx[r][a] = feat[row * Dn + a];
                __syncthreads();
                float av = __ldg(&bw[a]);
                #pragma unroll
                for (int k = 0; k < Dn; k++)
                    av += sm.s1.sx[r][k] * __ldg(&Ww[k * Dn + a]);
                const float wua = __ldg(&Wu[a]);
                g_pre_f[row * Dn + a] = av;
                g_P1[row * Dn + a] = wua * av * av;
                g_P2[row * Dn + a] = wua * av;
                float mm = fabsf(av);
                #pragma unroll
                for (int off = 16; off > 0; off >>= 1)
                    mm = fmaxf(mm, __shfl_xor_sync(0xffffffffu, mm, off));
                if (lane == 0) sm.s1.rmax[wid] = mm;
                __syncthreads();
                if (tid == 0)  g_amax[row] = fmaxf(sm.s1.rmax[0], sm.s1.rmax[1]);
                if (tid == 64) g_amax[row] = fmaxf(sm.s1.rmax[2], sm.s1.rmax[3]);
            }
        }
    }

    grid_bar();

    // ============ Stage 2: masked attention -> ctx (1 row per block) ========
    for (int i = blockIdx.x; i < Fn; i += NB) {
        if (tid < Dn) {
            sm.s2.P1[tid] = g_P1[i * Dn + tid];
            sm.s2.P2[tid] = g_P2[i * Dn + tid];
            sm.s2.pf[tid] = g_pre_f[i * Dn + tid];
            sm.s2.wu[tid] = __ldg(&Wu[tid]);
        }
        __syncthreads();

        // sum |wu| (warp 0)
        if (wid == 0) {
            float s = fabsf(sm.s2.wu[lane]) + fabsf(sm.s2.wu[lane + 32]);
            #pragma unroll
            for (int off = 16; off > 0; off >>= 1)
                s += __shfl_xor_sync(0xffffffffu, s, off);
            if (lane == 0) sm.s2.swu_s = s;
        }

        // ---- Phase A: compaction (20 chunks of 128)
        const float* mrow = mask + (size_t)i * FH;
        unsigned flags = 0;
        #pragma unroll
        for (int c = 0; c < 20; c++) {
            int j = c * 128 + tid;
            if (j < FH && mrow[j] != 0.0f) flags |= (1u << c);
        }
        const int cl = __popc(flags);
        int inc = cl;
        #pragma unroll
        for (int off = 1; off < 32; off <<= 1) {
            int v = __shfl_up_sync(0xffffffffu, inc, off);
            if (lane >= off) inc += v;
        }
        if (lane == 31) sm.s2.warpbase[wid + 1] = inc;
        __syncthreads();
        if (tid == 0) {
            sm.s2.warpbase[0] = 0;
            #pragma unroll
            for (int w = 1; w <= 4; w++)
                sm.s2.warpbase[w] += sm.s2.warpbase[w - 1];
        }
        __syncthreads();
        {
            int off = sm.s2.warpbase[wid] + inc - cl;
            #pragma unroll
            for (int c = 0; c < 20; c++)
                if ((flags >> c) & 1u)
                    sm.s2.jlist[off++] = (unsigned short)(c * 128 + tid);
        }
        __syncthreads();
        const int cnt = sm.s2.warpbase[4];

        // ---- guard: level 0 bilinear / 1 poly / 2 exact
        {
            float mxb = 0.f;
            for (int m = tid; m < cnt; m += 128)
                mxb = fmaxf(mxb, __ldg(&g_pwmax[(int)sm.s2.jlist[m]]));
            #pragma unroll
            for (int off = 16; off > 0; off >>= 1)
                mxb = fmaxf(mxb, __shfl_xor_sync(0xffffffffu, mxb, off));
            if (lane == 0) sm.s2.red4[wid] = mxb;
            __syncthreads();
            if (tid == 0) {
                float m2 = fmaxf(fmaxf(sm.s2.red4[0], sm.s2.red4[1]),
                                 fmaxf(sm.s2.red4[2], sm.s2.red4[3]));
                float bnd = g_amax[i] + m2;
                float b5 = bnd * bnd; b5 = b5 * b5 * bnd;
                float err = 0.1333333f * b5 * sm.s2.swu_s;
                sm.s2.level = (err < 1e-4f) ? 0 : ((bnd < 0.45f) ? 1 : 2);
            }
            __syncthreads();
        }

        // ---- Phase B
        float wsum = 0.f;
        const int level = sm.s2.level;
        if (level == 0) {
            const ull* P1u = (const ull*)sm.s2.P1;
            const ull* P2u = (const ull*)sm.s2.P2;
            for (int m = tid; m < cnt; m += 128) {
                const int j = sm.s2.jlist[m];
                const float4* br = (const float4*)(g_pre_w + j * Dn);
                const float Bj = __ldg(&g_B[j]);
                ull acc = 0ull;
                #pragma unroll
                for (int q = 0; q < 16; q++) {
                    float4 b4 = __ldg(br + q);
                    ull b01 = pk2(b4.x, b4.y);
                    ull b23 = pk2(b4.z, b4.w);
                    ull t01 = f2fma(P2u[2 * q],     b01, P1u[2 * q]);
                    ull t23 = f2fma(P2u[2 * q + 1], b23, P1u[2 * q + 1]);
                    acc = f2fma(t01, b01, acc);
                    acc = f2fma(t23, b23, acc);
                }
                float d0, d1; upk2(acc, d0, d1);
                float e = __expf(Bj - (d0 + d1));
                sm.s2.elist[m] = e;
                wsum += e;
            }
        } else if (level == 1) {
            const ull C3  = pk2(-0.33333334f, -0.33333334f);
            const ull C5  = pk2( 0.13333334f,  0.13333334f);
            const ull C7  = pk2(-0.05396825f, -0.05396825f);
            const ull ONE = pk2(1.0f, 1.0f);
            const float4* pf4 = (const float4*)sm.s2.pf;
            const float4* wu4 = (const float4*)sm.s2.wu;
            for (int m = tid; m < cnt; m += 128) {
                const int j = sm.s2.jlist[m];
                const float4* pr = (const float4*)(g_pre_w + j * Dn);
                ull acc = 0ull;
                #pragma unroll
                for (int q = 0; q < 16; q++) {
                    float4 pw = __ldg(pr + q);
                    float4 pf = pf4[q];
                    float4 wu = wu4[q];
                    ull x01 = pk2(pf.x + pw.x, pf.y + pw.y);
                    ull x23 = pk2(pf.z + pw.z, pf.w + pw.w);
                    ull t01 = f2mul(x01, x01);
                    ull t23 = f2mul(x23, x23);
                    ull p01 = f2fma(t01, C7, C5);
                    ull p23 = f2fma(t23, C7, C5);
                    p01 = f2fma(t01, p01, C3);
                    p23 = f2fma(t23, p23, C3);
                    p01 = f2fma(t01, p01, ONE);
                    p23 = f2fma(t23, p23, ONE);
                    acc = f2fma(f2mul(x01, p01), pk2(wu.x, wu.y), acc);
                    acc = f2fma(f2mul(x23, p23), pk2(wu.z, wu.w), acc);
                }
                float a0, a1; upk2(acc, a0, a1);
                float e = __expf(a0 + a1);
                sm.s2.elist[m] = e;
                wsum += e;
            }
        } else {
            for (int m = tid; m < cnt; m += 128) {
                const int j = sm.s2.jlist[m];
                const float* pr = g_pre_w + j * Dn;
                float s = 0.f;
                for (int k = 0; k < Dn; k++)
                    s += tanhf(sm.s2.pf[k] + pr[k]) * sm.s2.wu[k];
                float e = expf(s);
                sm.s2.elist[m] = e;
                wsum += e;
            }
        }
        #pragma unroll
        for (int off = 16; off > 0; off >>= 1)
            wsum += __shfl_xor_sync(0xffffffffu, wsum, off);
        if (lane == 0) sm.s2.wsum[wid] = wsum;
        __syncthreads();
        if (tid == 0) {
            float ss = (sm.s2.wsum[0] + sm.s2.wsum[1]) +
                       (sm.s2.wsum[2] + sm.s2.wsum[3]);
            sm.s2.inv = (ss > 0.f) ? (1.0f / ss) : 1.0f;
        }
        __syncthreads();

        // ---- Phase C: gather-accumulate, 8 independent chains
        {
            const int g = tid >> 6;       // 0/1
            const int k = tid & 63;
            float a0 = 0.f, a1 = 0.f, a2 = 0.f, a3 = 0.f;
            float a4 = 0.f, a5 = 0.f, a6 = 0.f, a7 = 0.f;
            int m = g;
            for (; m + 14 < cnt; m += 16) {
                a0 += sm.s2.elist[m]      * __ldg(full_row(feat, hid, sm.s2.jlist[m])      + k);
                a1 += sm.s2.elist[m + 2]  * __ldg(full_row(feat, hid, sm.s2.jlist[m + 2])  + k);
                a2 += sm.s2.elist[m + 4]  * __ldg(full_row(feat, hid, sm.s2.jlist[m + 4])  + k);
                a3 += sm.s2.elist[m + 6]  * __ldg(full_row(feat, hid, sm.s2.jlist[m + 6])  + k);
                a4 += sm.s2.elist[m + 8]  * __ldg(full_row(feat, hid, sm.s2.jlist[m + 8])  + k);
                a5 += sm.s2.elist[m + 10] * __ldg(full_row(feat, hid, sm.s2.jlist[m + 10]) + k);
                a6 += sm.s2.elist[m + 12] * __ldg(full_row(feat, hid, sm.s2.jlist[m + 12]) + k);
                a7 += sm.s2.elist[m + 14] * __ldg(full_row(feat, hid, sm.s2.jlist[m + 14]) + k);
            }
            for (; m < cnt; m += 2)
                a0 += sm.s2.elist[m] * __ldg(full_row(feat, hid, sm.s2.jlist[m]) + k);
            sm.s2.part[g][k] = ((a0 + a1) + (a2 + a3)) + ((a4 + a5) + (a6 + a7));
            __syncthreads();
            if (tid < Dn)
                g_ctx[i * Dn + tid] =
                    (sm.s2.part[0][tid] + sm.s2.part[1][tid]) * sm.s2.inv;
        }
    }

    grid_bar();

    // ============ Stage 3: out = values @ ctx (512 blocks x 8 rows) =========
    for (int rb = blockIdx.x; rb < 512; rb += NB) {
        const int tx   = tid & 15;
        const int ty   = tid >> 4;       // 0..7 -> row
        const int col0 = tx * 4;
        const int row  = rb * 8 + ty;

        ull a0 = 0ull, a1 = 0ull;

        for (int f0 = 0; f0 < Fn; f0 += TFk) {
            for (int idx = tid; idx < 8 * TFk; idx += 128) {
                int r = idx / TFk, f = idx % TFk;
                sm.s3.val[r][f] = values[(size_t)(rb * 8 + r) * Fn + f0 + f];
            }
            for (int idx = tid; idx < TFk * Dn; idx += 128) {
                int f = idx >> 6, c = idx & 63;
                sm.s3.ctx[f][c] = g_ctx[(f0 + f) * Dn + c];
            }
            __syncthreads();

            #pragma unroll
            for (int f = 0; f < TFk; f++) {
                float v = sm.s3.val[ty][f];
                ull vp = pk2(v, v);
                const ull* cp = reinterpret_cast<const ull*>(&sm.s3.ctx[f][col0]);
                a0 = f2fma(vp, cp[0], a0);
                a1 = f2fma(vp, cp[1], a1);
            }
            __syncthreads();
        }

        float a, b, c, d;
        upk2(a0, a, b); upk2(a1, c, d);
        *reinterpret_cast<float4*>(&out[(size_t)row * Dn + col0]) =
            make_float4(a, b, c, d);
    }
}

extern "C" void kernel_launch(void* const* d_in, const int* in_sizes, int n_in,
                              void* d_out, int out_size)
{
    const float* values   = (const float*)d_in[0];
    const float* feat_emb = (const float*)d_in[1];
    const float* hid_emb  = (const float*)d_in[2];
    const float* Ww       = (const float*)d_in[3];
    const float* bw       = (const float*)d_in[4];
    const float* Wu       = (const float*)d_in[5];
    const float* mask     = (const float*)d_in[6];
    float* out            = (float*)d_out;

    fused_all<<<NB, 128>>>(values, feat_emb, hid_emb, Ww, bw, Wu, mask, out);
}